// round 13
// baseline (speedup 1.0000x reference)
#include <cuda_runtime.h>
#include <math_constants.h>
#include <stdint.h>

#define NB    8
#define NPTS  4096
#define KNN   20
#define CH    64
#define NSAMP (NB*NPTS*KNN)      // 655360
#define NQ    (NB*NPTS)          // 32768 queries
#define NSEG  4
#define SEGN  (NPTS/NSEG)        // 1024
#define BN_EPS 1e-5
#define SLOPE  0.2f
#define YPITCH 32                // 8 float4 chunks; XOR swizzle vs (ca&7)

// ---------------- device scratch ----------------
__device__ float4 g_packed[NB*NPTS];                 // (x,y,z,|p|^2)
__device__ float4 g_E4[NSAMP];                       // edge diffs (d3, 0)
__device__ float  g_dl[NSEG*NQ*KNN];                 // per-segment sorted dists
__device__ double g_S1[6];
__device__ double g_S2[21];
__device__ float  g_W1f[CH*6];
__device__ float  g_c1[CH];
__device__ double g_h2sum[CH];
__device__ double g_h2sq[CH];
__device__ float  g_a2[CH], g_c2[CH];
__device__ float  g_hmax[(size_t)NQ*CH];
__device__ float  g_hmin[(size_t)NQ*CH];
__device__ int    g_ctr;

// ---------------- packed f32x2 helpers ----------------
__device__ __forceinline__ unsigned long long fma2(unsigned long long a,
                                                   unsigned long long b,
                                                   unsigned long long c) {
    unsigned long long d;
    asm("fma.rn.f32x2 %0, %1, %2, %3;" : "=l"(d) : "l"(a), "l"(b), "l"(c));
    return d;
}
__device__ __forceinline__ unsigned long long pack2(float x) {
    unsigned long long d;
    asm("mov.b64 %0, {%1, %1};" : "=l"(d) : "f"(x));
    return d;
}
__device__ __forceinline__ void unpack2(unsigned long long v, float& lo, float& hi) {
    asm("mov.b64 {%0, %1}, %2;" : "=f"(lo), "=f"(hi) : "l"(v));
}

// ---------------- dummy (ncu lands on launch index 3 -> k1_seg) --------
__global__ void kdummy() {}

// ---------------- K0: pack points + zero accumulators ----------------
__global__ void k0_pack(const float* __restrict__ a) {
    int t = blockIdx.x*blockDim.x + threadIdx.x;     // 0..32767
    int b = t / NPTS, n = t % NPTS;
    const float* ab = a + (size_t)b*3*NPTS;
    float x = ab[n], y = ab[NPTS+n], z = ab[2*NPTS+n];
    float sq = fmaf(z,z, fmaf(y,y, x*x));
    g_packed[t] = make_float4(x,y,z,sq);
    if (blockIdx.x == 0) {
        int i = threadIdx.x;
        if (i == 0)  g_ctr = 0;
        if (i < 6)   g_S1[i] = 0.0;
        if (i < 21)  g_S2[i] = 0.0;
        if (i < CH) { g_h2sum[i] = 0.0; g_h2sq[i] = 0.0; }
    }
}

// ---------------- K1a: 4-segment distance-only top-20 ------------------
// d' = sq_j - 2*dot(p_i,p_j). Branchless sorted-insert network:
//   dl[t] = min(dl[t], max(d, dl[t-1]))   (exact, 2 FMNMX/slot, no preds)
__global__ void __launch_bounds__(128) k1_seg() {
    int blk = blockIdx.x;                            // 0..1023
    int seg = blk >> 8;                              // 0..3
    int qid = (blk & 255)*128 + threadIdx.x;         // 0..32767
    int b = qid / NPTS; int i = qid % NPTS;
    const float4* pts = &g_packed[b*NPTS];
    float4 pi = pts[i];
    float n2x = -2.f*pi.x, n2y = -2.f*pi.y, n2z = -2.f*pi.z;

    float dl[KNN];
    #pragma unroll
    for (int t = 0; t < KNN; t++) dl[t] = CUDART_INF_F;

    int jbase = seg * SEGN;
    for (int j = 0; j < SEGN; j += 8) {
        float dd[8];
        #pragma unroll
        for (int u = 0; u < 8; u++) {
            float4 pj = __ldg(&pts[jbase + j + u]);
            dd[u] = fmaf(n2z, pj.z, fmaf(n2y, pj.y, fmaf(n2x, pj.x, pj.w)));
        }
        #pragma unroll
        for (int u = 0; u < 8; u++) {
            float d = dd[u];
            if (d < dl[KNN-1]) {
                #pragma unroll
                for (int t = KNN-1; t >= 1; t--)
                    dl[t] = fminf(dl[t], fmaxf(d, dl[t-1]));
                dl[0] = fminf(dl[0], d);
            }
        }
    }
    size_t o = ((size_t)seg*NQ + qid)*KNN;
    #pragma unroll
    for (int t = 0; t < KNN; t++) g_dl[o+t] = dl[t];
}

// ---------------- K1b: warp-coop rescan + emit + moments + BN1 fold ----
// thr = exact 20th smallest over the 4 sorted segment lists: lanes 0..3
// hold list heads; 20 steps of warp-min with lane-order tie-breaking so
// duplicate values advance exactly one list per step (multiset-exact).
__global__ void __launch_bounds__(256) k1_emit(const float* __restrict__ W1,
                                               const float* __restrict__ g1,
                                               const float* __restrict__ b1) {
    __shared__ int   ties[8][KNN];
    __shared__ float sS1[6], sS2[21];
    __shared__ int   isLast;
    int wid  = threadIdx.x >> 5;
    int lane = threadIdx.x & 31;
    int qid  = blockIdx.x*8 + wid;                   // one query per warp
    int b = qid / NPTS; int i = qid % NPTS;
    const float4* pts = &g_packed[b*NPTS];
    float4 pi = pts[i];
    float n2x = -2.f*pi.x, n2y = -2.f*pi.y, n2z = -2.f*pi.z;

    if (threadIdx.x < 6)  sS1[threadIdx.x] = 0.f;
    if (threadIdx.x < 21) sS2[threadIdx.x] = 0.f;
    __syncthreads();

    // 4-way merge across lanes 0..3 to find 20th smallest value
    const float* Lp = &g_dl[((size_t)(lane & 3)*NQ + qid)*KNN];
    float hd = (lane < NSEG) ? Lp[0] : CUDART_INF_F;
    int   ii = 0;
    float thr = 0.f;
    #pragma unroll
    for (int t = 0; t < KNN; t++) {
        float m = hd;
        m = fminf(m, __shfl_xor_sync(~0u, m, 1));
        m = fminf(m, __shfl_xor_sync(~0u, m, 2));
        m = __shfl_sync(~0u, m, 0);                  // min of lanes 0..3
        thr = m;
        unsigned eqm = __ballot_sync(~0u, (lane < NSEG) && (hd == m));
        int owner = __ffs(eqm) - 1;
        if (lane == owner) {
            ii++;
            hd = (ii < KNN) ? Lp[ii] : CUDART_INF_F;
        }
    }

    float4* E = &g_E4[(size_t)qid*KNN];
    int m = 0, tcnt = 0;
    float sdx=0.f, sdy=0.f, sdz=0.f;
    float sxx=0.f, sxy=0.f, sxz=0.f, syy=0.f, syz=0.f, szz=0.f;

    float4 pj = __ldg(&pts[lane]);                   // prefetch
    for (int it = 0; it < NPTS/32; it++) {
        float4 cur = pj;
        if (it < NPTS/32 - 1) pj = __ldg(&pts[(it+1)*32 + lane]);
        float d = fmaf(n2z, cur.z, fmaf(n2y, cur.y, fmaf(n2x, cur.x, cur.w)));
        unsigned le = __ballot_sync(~0u, d <= thr);
        if (le) {
            unsigned lt = __ballot_sync(~0u, d < thr);
            unsigned eq = le & ~lt;
            unsigned below = (1u << lane) - 1u;
            if (d < thr) {
                float dx = cur.x-pi.x, dy = cur.y-pi.y, dz = cur.z-pi.z;
                E[m + __popc(lt & below)] = make_float4(dx, dy, dz, 0.f);
                sdx += dx; sdy += dy; sdz += dz;
                sxx = fmaf(dx,dx,sxx); sxy = fmaf(dx,dy,sxy); sxz = fmaf(dx,dz,sxz);
                syy = fmaf(dy,dy,syy); syz = fmaf(dy,dz,syz); szz = fmaf(dz,dz,szz);
            } else if (eq & (1u << lane)) {
                int pos = tcnt + __popc(eq & below);
                if (pos < KNN) ties[wid][pos] = it*32 + lane;
            }
            m    += __popc(lt);
            tcnt += __popc(eq);
        }
    }
    __syncwarp();
    int need = KNN - m;                              // >= 1, tcnt >= need
    if (lane < need) {
        float4 pt = pts[ties[wid][lane]];
        float dx = pt.x-pi.x, dy = pt.y-pi.y, dz = pt.z-pi.z;
        E[m + lane] = make_float4(dx, dy, dz, 0.f);
        sdx += dx; sdy += dy; sdz += dz;
        sxx = fmaf(dx,dx,sxx); sxy = fmaf(dx,dy,sxy); sxz = fmaf(dx,dz,sxz);
        syy = fmaf(dy,dy,syy); syz = fmaf(dy,dz,syz); szz = fmaf(dz,dz,szz);
    }
    #pragma unroll
    for (int o = 16; o > 0; o >>= 1) {
        sdx += __shfl_xor_sync(~0u, sdx, o); sdy += __shfl_xor_sync(~0u, sdy, o);
        sdz += __shfl_xor_sync(~0u, sdz, o);
        sxx += __shfl_xor_sync(~0u, sxx, o); sxy += __shfl_xor_sync(~0u, sxy, o);
        sxz += __shfl_xor_sync(~0u, sxz, o);
        syy += __shfl_xor_sync(~0u, syy, o); syz += __shfl_xor_sync(~0u, syz, o);
        szz += __shfl_xor_sync(~0u, szz, o);
    }
    if (lane == 0) {
        float px = pi.x, py = pi.y, pz = pi.z;
        float Kf = (float)KNN;
        atomicAdd(&sS1[0], sdx); atomicAdd(&sS1[1], sdy); atomicAdd(&sS1[2], sdz);
        atomicAdd(&sS1[3], Kf*px); atomicAdd(&sS1[4], Kf*py); atomicAdd(&sS1[5], Kf*pz);
        atomicAdd(&sS2[0],  sxx);      atomicAdd(&sS2[1],  sxy);
        atomicAdd(&sS2[2],  sxz);      atomicAdd(&sS2[3],  sdx*px);
        atomicAdd(&sS2[4],  sdx*py);   atomicAdd(&sS2[5],  sdx*pz);
        atomicAdd(&sS2[6],  syy);      atomicAdd(&sS2[7],  syz);
        atomicAdd(&sS2[8],  sdy*px);   atomicAdd(&sS2[9],  sdy*py);
        atomicAdd(&sS2[10], sdy*pz);   atomicAdd(&sS2[11], szz);
        atomicAdd(&sS2[12], sdz*px);   atomicAdd(&sS2[13], sdz*py);
        atomicAdd(&sS2[14], sdz*pz);   atomicAdd(&sS2[15], Kf*px*px);
        atomicAdd(&sS2[16], Kf*px*py); atomicAdd(&sS2[17], Kf*px*pz);
        atomicAdd(&sS2[18], Kf*py*py); atomicAdd(&sS2[19], Kf*py*pz);
        atomicAdd(&sS2[20], Kf*pz*pz);
    }
    __syncthreads();
    if (threadIdx.x < 6)  atomicAdd(&g_S1[threadIdx.x], (double)sS1[threadIdx.x]);
    if (threadIdx.x < 21) atomicAdd(&g_S2[threadIdx.x], (double)sS2[threadIdx.x]);

    __threadfence();
    if (threadIdx.x == 0)
        isLast = (atomicAdd(&g_ctr, 1) == (int)gridDim.x - 1);
    __syncthreads();
    if (isLast) {
        int o = threadIdx.x;
        if (o < CH) {
            const float M = (float)NSAMP;
            float m1[6];
            #pragma unroll
            for (int c = 0; c < 6; c++) m1[c] = (float)g_S1[c] / M;
            float w[6];
            #pragma unroll
            for (int c = 0; c < 6; c++) w[c] = W1[o*6 + c];
            float mean = 0.f;
            #pragma unroll
            for (int c = 0; c < 6; c++) mean = fmaf(w[c], m1[c], mean);
            float e2 = 0.f;
            int q = 0;
            #pragma unroll
            for (int c1 = 0; c1 < 6; c1++)
                #pragma unroll
                for (int c2 = c1; c2 < 6; c2++) {
                    float t2 = w[c1]*w[c2]*((float)g_S2[q] / M);
                    e2 += (c1 == c2) ? t2 : 2.f*t2;
                    q++;
                }
            float var = e2 - mean*mean;
            float aa = g1[o] * rsqrtf(var + (float)BN_EPS);
            g_c1[o] = b1[o] - mean*aa;
            #pragma unroll
            for (int c = 0; c < 6; c++) g_W1f[o*6 + c] = aa*w[c];
        }
        if (threadIdx.x == 0) g_ctr = 0;            // reset for next replay
    }
}

// ---------------- K3: fused MLP, swizzled y1 staging -------------------
// y1s layout: [pw][ca][chunk^  ] where physical chunk = (k>>2) ^ (ca&7);
// phase A writes 6 conflict-free STS.128 per point (8 columns tile all
// 32 banks); phase B reads 16B-aligned swizzled chunks (broadcast).
#define PPB3 16
__global__ void __launch_bounds__(256, 2) k3_mlp(const float* __restrict__ W2) {
    extern __shared__ float smem[];
    float* sW2  = smem;                              // [c*64+u], 16KB
    float* y1s  = smem + CH*CH;                      // [pw][ca*32+*], 64KB
    float* ssum = y1s + 8*CH*YPITCH;                 // [64]
    float* ssq  = ssum + CH;                         // [64]

    int t = threadIdx.x;
    if (t < CH) { ssum[t] = 0.f; ssq[t] = 0.f; }
    for (int s = t; s < CH*CH; s += 256) {
        int u = s & 63, c = s >> 6;
        sW2[c*CH + u] = W2[u*CH + c];
    }
    // phase A identity
    int pa = t >> 6, ca = t & 63;
    int sw = ca & 7;
    float w1r[6];
    #pragma unroll
    for (int c = 0; c < 6; c++) w1r[c] = g_W1f[ca*6 + c];
    float c1v = g_c1[ca];
    // phase B identity
    int warp = t >> 5, lane = t & 31;
    int ug = lane & 15, kq = lane >> 4;
    int u0 = ug*4;
    float su[4] = {0,0,0,0}, qu[4] = {0,0,0,0};
    __syncthreads();

    for (int ph = 0; ph < 2; ph++) {
        int pbase = blockIdx.x*PPB3 + ph*8;
        // ---- phase A ----
        #pragma unroll
        for (int pp = 0; pp < 2; pp++) {
            int pw = pa + pp*4;
            int p  = pbase + pw;
            float4 pt = g_packed[p];
            float base = c1v;
            base = fmaf(w1r[3], pt.x, base);
            base = fmaf(w1r[4], pt.y, base);
            base = fmaf(w1r[5], pt.z, base);
            const float4* Ep = &g_E4[(size_t)p*KNN];
            float yv[24];
            #pragma unroll
            for (int k = 0; k < KNN; k++) {
                float4 v = Ep[k];
                float h = base;
                h = fmaf(w1r[0], v.x, h);
                h = fmaf(w1r[1], v.y, h);
                h = fmaf(w1r[2], v.z, h);
                yv[k] = (h >= 0.f) ? h : SLOPE*h;
            }
            #pragma unroll
            for (int k = KNN; k < 24; k++) yv[k] = 0.f;
            float* yo = &y1s[pw*CH*YPITCH + ca*YPITCH];
            #pragma unroll
            for (int c4 = 0; c4 < 6; c4++) {
                int chunk = c4 ^ sw;
                *(float4*)(yo + chunk*4) =
                    make_float4(yv[4*c4], yv[4*c4+1], yv[4*c4+2], yv[4*c4+3]);
            }
        }
        __syncthreads();
        // ---- phase B: warp-per-point, 4u x 12k per lane ----
        int p = pbase + warp;
        const float* yb = &y1s[warp*CH*YPITCH];
        unsigned long long acc[4][6];
        #pragma unroll
        for (int uu = 0; uu < 4; uu++)
            #pragma unroll
            for (int kk = 0; kk < 6; kk++) acc[uu][kk] = 0ull;
        #pragma unroll 4
        for (int c = 0; c < CH; c++) {
            float4 wv = *(const float4*)&sW2[c*CH + u0];
            unsigned long long w0 = pack2(wv.x), w1 = pack2(wv.y);
            unsigned long long w2 = pack2(wv.z), w3 = pack2(wv.w);
            const float* yr = yb + c*YPITCH;
            int cs = c & 7;
            #pragma unroll
            for (int q = 0; q < 3; q++) {
                int chunk = (3*kq + q) ^ cs;
                ulonglong2 yv = *(const ulonglong2*)(yr + chunk*4);
                acc[0][2*q]   = fma2(w0, yv.x, acc[0][2*q]);
                acc[1][2*q]   = fma2(w1, yv.x, acc[1][2*q]);
                acc[2][2*q]   = fma2(w2, yv.x, acc[2][2*q]);
                acc[3][2*q]   = fma2(w3, yv.x, acc[3][2*q]);
                acc[0][2*q+1] = fma2(w0, yv.y, acc[0][2*q+1]);
                acc[1][2*q+1] = fma2(w1, yv.y, acc[1][2*q+1]);
                acc[2][2*q+1] = fma2(w2, yv.y, acc[2][2*q+1]);
                acc[3][2*q+1] = fma2(w3, yv.y, acc[3][2*q+1]);
            }
        }
        float mx[4], mn[4];
        #pragma unroll
        for (int uu = 0; uu < 4; uu++) {
            mx[uu] = -CUDART_INF_F; mn[uu] = CUDART_INF_F;
            #pragma unroll
            for (int kk = 0; kk < 6; kk++) {
                bool valid = (kq == 0) || (kk < 4);   // kq=1 kk=4,5 are k20..23 pads
                float lo, hi;
                unpack2(acc[uu][kk], lo, hi);
                su[uu] += lo + hi;                    // pads add 0: harmless
                qu[uu] = fmaf(lo, lo, fmaf(hi, hi, qu[uu]));
                float cmx = valid ? fmaxf(lo, hi) : -CUDART_INF_F;
                float cmn = valid ? fminf(lo, hi) :  CUDART_INF_F;
                mx[uu] = fmaxf(mx[uu], cmx);
                mn[uu] = fminf(mn[uu], cmn);
            }
        }
        #pragma unroll
        for (int uu = 0; uu < 4; uu++) {
            mx[uu] = fmaxf(mx[uu], __shfl_down_sync(~0u, mx[uu], 16));
            mn[uu] = fminf(mn[uu], __shfl_down_sync(~0u, mn[uu], 16));
        }
        if (lane < 16) {
            *(float4*)&g_hmax[(size_t)p*CH + u0] = make_float4(mx[0],mx[1],mx[2],mx[3]);
            *(float4*)&g_hmin[(size_t)p*CH + u0] = make_float4(mn[0],mn[1],mn[2],mn[3]);
        }
        __syncthreads();                 // y1s reuse next ph
    }
    // BN2 stats
    #pragma unroll
    for (int uu = 0; uu < 4; uu++) {
        atomicAdd(&ssum[u0+uu], su[uu]);
        atomicAdd(&ssq[u0+uu],  qu[uu]);
    }
    __syncthreads();
    if (t < CH) {
        atomicAdd(&g_h2sum[t], (double)ssum[t]);
        atomicAdd(&g_h2sq[t],  (double)ssq[t]);
    }
}

// ---------------- F2: finalize BN2 ----------------
__global__ void f2_fold(const float* __restrict__ g2, const float* __restrict__ b2) {
    int o = threadIdx.x; if (o >= CH) return;
    double M = (double)NSAMP;
    double m = g_h2sum[o] / M;
    double v = g_h2sq[o] / M - m*m;
    double a = (double)g2[o] / sqrt(v + BN_EPS);
    g_a2[o] = (float)a;
    g_c2[o] = (float)((double)b2[o] - m*a);
}

// ---------------- K5: BN2+lrelu via monotone max/min + transpose -------
__global__ void k5_out(float* __restrict__ out) {
    __shared__ float tile[32][33];
    int b = blockIdx.z;
    int n0 = blockIdx.x*32, o0 = blockIdx.y*32;
    int tx = threadIdx.x, ty = threadIdx.y;
    #pragma unroll
    for (int r = 0; r < 4; r++) {
        int n = n0 + ty + 8*r, o = o0 + tx;
        float a = g_a2[o], c = g_c2[o];
        size_t idx = ((size_t)(b*NPTS + n))*CH + o;
        float h = (a >= 0.f) ? g_hmax[idx] : g_hmin[idx];
        float v = fmaf(a, h, c);
        tile[ty + 8*r][tx] = (v >= 0.f) ? v : SLOPE*v;
    }
    __syncthreads();
    #pragma unroll
    for (int r = 0; r < 4; r++) {
        int o = o0 + ty + 8*r, n = n0 + tx;
        out[((size_t)(b*CH + o))*NPTS + n] = tile[tx][ty + 8*r];
    }
}

// ---------------- launch ----------------
extern "C" void kernel_launch(void* const* d_in, const int* in_sizes, int n_in,
                              void* d_out, int out_size) {
    const float* a  = (const float*)d_in[0];
    const float* W1 = (const float*)d_in[1];
    const float* g1 = (const float*)d_in[2];
    const float* b1 = (const float*)d_in[3];
    const float* W2 = (const float*)d_in[4];
    const float* g2 = (const float*)d_in[5];
    const float* b2 = (const float*)d_in[6];
    float* out = (float*)d_out;

    const int K3_SMEM = (CH*CH + 8*CH*YPITCH + 2*CH + 32) * 4;  // ~82.6KB
    cudaFuncSetAttribute(k3_mlp, cudaFuncAttributeMaxDynamicSharedMemorySize, K3_SMEM);

    // 2 dummies: ncu capture lands on launch index 3 == k1_seg
    kdummy<<<1, 32>>>();                             // index 0
    kdummy<<<1, 32>>>();                             // index 1
    k0_pack<<<128, 256>>>(a);                        // index 2
    k1_seg<<<1024, 128>>>();                         // index 3  <- profiled
    k1_emit<<<4096, 256>>>(W1, g1, b1);              // index 4
    k3_mlp<<<2048, 256, K3_SMEM>>>(W2);              // index 5
    f2_fold<<<1, 64>>>(g2, b2);                      // index 6
    k5_out<<<dim3(128, 2, NB), dim3(32, 8)>>>(out);  // index 7
}

// round 16
// speedup vs baseline: 1.0064x; 1.0064x over previous
#include <cuda_runtime.h>
#include <math_constants.h>
#include <stdint.h>

#define NB    8
#define NPTS  4096
#define KNN   20
#define CH    64
#define NSAMP (NB*NPTS*KNN)      // 655360
#define NQ    (NB*NPTS)          // 32768 queries
#define NSEG  2
#define SEGN  (NPTS/NSEG)        // 2048
#define BN_EPS 1e-5
#define SLOPE  0.2f
#define YPITCH 28                // float4-aligned every c; gcd(28,32)=4

// ---------------- device scratch ----------------
__device__ float4     g_packed[NB*NPTS];             // (x,y,z,|p|^2)
__device__ ulonglong2 g_pk[NB*NPTS];                 // pair-packed {x2,y2},{z2,w2}
__device__ float4     g_E4[NSAMP];                   // edge diffs (d3, 0)
__device__ float      g_dl[NSEG*NQ*KNN];             // per-segment sorted dists
__device__ double     g_S1[6];
__device__ double     g_S2[21];
__device__ float      g_W1f[CH*6];
__device__ float      g_c1[CH];
__device__ double     g_h2sum[CH];
__device__ double     g_h2sq[CH];
__device__ float      g_a2[CH], g_c2[CH];
__device__ float      g_hmax[(size_t)NQ*CH];
__device__ float      g_hmin[(size_t)NQ*CH];
__device__ int        g_ctr;

// ---------------- packed f32x2 helpers ----------------
__device__ __forceinline__ unsigned long long fma2(unsigned long long a,
                                                   unsigned long long b,
                                                   unsigned long long c) {
    unsigned long long d;
    asm("fma.rn.f32x2 %0, %1, %2, %3;" : "=l"(d) : "l"(a), "l"(b), "l"(c));
    return d;
}
__device__ __forceinline__ unsigned long long pack2(float x) {
    unsigned long long d;
    asm("mov.b64 %0, {%1, %1};" : "=l"(d) : "f"(x));
    return d;
}
__device__ __forceinline__ void unpack2(unsigned long long v, float& lo, float& hi) {
    asm("mov.b64 {%0, %1}, %2;" : "=f"(lo), "=f"(hi) : "l"(v));
}

// ---------------- dummy (ncu lands on launch index 3 -> k1_seg) --------
__global__ void kdummy() {}

// ---------------- K0: pack points (both layouts) + zero accumulators ---
// pair-packed: pair g occupies g_pk[2g] = {x2, y2}, g_pk[2g+1] = {z2, w2},
// where e.g. x2 packs x of candidates (2g, 2g+1) in (lo, hi).
__global__ void k0_pack(const float* __restrict__ a) {
    int t = blockIdx.x*blockDim.x + threadIdx.x;     // 0..32767
    int b = t / NPTS, n = t % NPTS;
    const float* ab = a + (size_t)b*3*NPTS;
    float x = ab[n], y = ab[NPTS+n], z = ab[2*NPTS+n];
    float sq = fmaf(z,z, fmaf(y,y, x*x));
    g_packed[t] = make_float4(x,y,z,sq);
    {
        int half = n & 1;
        int g = n >> 1;
        float* pk = (float*)&g_pk[(size_t)(b*(NPTS/2) + g)*2];
        pk[0 + half] = x;   // x2
        pk[2 + half] = y;   // y2
        pk[4 + half] = z;   // z2
        pk[6 + half] = sq;  // w2
    }
    if (blockIdx.x == 0) {
        int i = threadIdx.x;
        if (i == 0)  g_ctr = 0;
        if (i < 6)   g_S1[i] = 0.0;
        if (i < 21)  g_S2[i] = 0.0;
        if (i < CH) { g_h2sum[i] = 0.0; g_h2sq[i] = 0.0; }
    }
}

// ---------------- K1a: segmented distance-only top-20 ------------------
// FFMA2 packed distances (per-lane fma chain bitwise-identical to emit's
// scalar chain). Sorted-insert network dl[t]=min(dl[t],max(d,dl[t-1]))
// with hierarchical short-cut: if d >= dl[9], slots 0..9 provably
// unchanged -> run only the 10-slot tail network.
__global__ void __launch_bounds__(128) k1_seg() {
    int blk = blockIdx.x;                            // 0..511
    int seg = (blk >= 256) ? 1 : 0;
    int qid = (blk & 255)*128 + threadIdx.x;         // 0..32767
    int b = qid / NPTS; int i = qid % NPTS;
    float4 pi = g_packed[b*NPTS + i];
    unsigned long long n2x2 = pack2(-2.f*pi.x);
    unsigned long long n2y2 = pack2(-2.f*pi.y);
    unsigned long long n2z2 = pack2(-2.f*pi.z);
    const ulonglong2* pk = &g_pk[(size_t)b*NPTS];    // 2 entries per pair

    float dl[KNN];
    #pragma unroll
    for (int t = 0; t < KNN; t++) dl[t] = CUDART_INF_F;

    int gbase = seg * (SEGN/2);
    for (int g = 0; g < SEGN/2; g += 4) {            // 4 pairs = 8 candidates
        unsigned long long d2[4];
        #pragma unroll
        for (int u = 0; u < 4; u++) {
            ulonglong2 cxy = __ldg(&pk[(gbase + g + u)*2]);
            ulonglong2 czw = __ldg(&pk[(gbase + g + u)*2 + 1]);
            d2[u] = fma2(n2z2, czw.x, fma2(n2y2, cxy.y, fma2(n2x2, cxy.x, czw.y)));
        }
        #pragma unroll
        for (int u = 0; u < 4; u++) {
            float dlo, dhi;
            unpack2(d2[u], dlo, dhi);
            #pragma unroll
            for (int h = 0; h < 2; h++) {
                float d = (h == 0) ? dlo : dhi;
                if (d < dl[KNN-1]) {
                    if (d >= dl[9]) {                // tail-only network
                        #pragma unroll
                        for (int t = KNN-1; t >= 10; t--)
                            dl[t] = fminf(dl[t], fmaxf(d, dl[t-1]));
                    } else {                         // full network
                        #pragma unroll
                        for (int t = KNN-1; t >= 1; t--)
                            dl[t] = fminf(dl[t], fmaxf(d, dl[t-1]));
                        dl[0] = fminf(dl[0], d);
                    }
                }
            }
        }
    }
    size_t o = ((size_t)seg*NQ + qid)*KNN;
    #pragma unroll
    for (int t = 0; t < KNN; t++) g_dl[o+t] = dl[t];
}

// ---------------- K1b: warp-coop rescan + emit + moments + BN1 fold ----
__global__ void __launch_bounds__(256) k1_emit(const float* __restrict__ W1,
                                               const float* __restrict__ g1,
                                               const float* __restrict__ b1) {
    __shared__ int   ties[8][KNN];
    __shared__ float sS1[6], sS2[21];
    __shared__ int   isLast;
    int wid  = threadIdx.x >> 5;
    int lane = threadIdx.x & 31;
    int qid  = blockIdx.x*8 + wid;                   // one query per warp
    int b = qid / NPTS; int i = qid % NPTS;
    const float4* pts = &g_packed[b*NPTS];
    float4 pi = pts[i];
    float n2x = -2.f*pi.x, n2y = -2.f*pi.y, n2z = -2.f*pi.z;

    if (threadIdx.x < 6)  sS1[threadIdx.x] = 0.f;
    if (threadIdx.x < 21) sS2[threadIdx.x] = 0.f;
    __syncthreads();

    float thr = 0.f;
    if (lane == 0) {
        const float* A = &g_dl[(size_t)qid*KNN];
        const float* B = &g_dl[((size_t)NQ + qid)*KNN];
        int ia = 0, ib = 0;
        float da = A[0], db = B[0];
        #pragma unroll
        for (int t = 0; t < KNN; t++) {
            bool ta = (da <= db);
            thr = ta ? da : db;
            if (ta) { ia++; da = (ia < KNN) ? A[ia] : CUDART_INF_F; }
            else    { ib++; db = (ib < KNN) ? B[ib] : CUDART_INF_F; }
        }
    }
    thr = __shfl_sync(~0u, thr, 0);

    float4* E = &g_E4[(size_t)qid*KNN];
    int m = 0, tcnt = 0;
    float sdx=0.f, sdy=0.f, sdz=0.f;
    float sxx=0.f, sxy=0.f, sxz=0.f, syy=0.f, syz=0.f, szz=0.f;

    float4 pj = __ldg(&pts[lane]);                   // prefetch
    for (int it = 0; it < NPTS/32; it++) {
        float4 cur = pj;
        if (it < NPTS/32 - 1) pj = __ldg(&pts[(it+1)*32 + lane]);
        float d = fmaf(n2z, cur.z, fmaf(n2y, cur.y, fmaf(n2x, cur.x, cur.w)));
        unsigned le = __ballot_sync(~0u, d <= thr);
        if (le) {
            unsigned lt = __ballot_sync(~0u, d < thr);
            unsigned eq = le & ~lt;
            unsigned below = (1u << lane) - 1u;
            if (d < thr) {
                float dx = cur.x-pi.x, dy = cur.y-pi.y, dz = cur.z-pi.z;
                E[m + __popc(lt & below)] = make_float4(dx, dy, dz, 0.f);
                sdx += dx; sdy += dy; sdz += dz;
                sxx = fmaf(dx,dx,sxx); sxy = fmaf(dx,dy,sxy); sxz = fmaf(dx,dz,sxz);
                syy = fmaf(dy,dy,syy); syz = fmaf(dy,dz,syz); szz = fmaf(dz,dz,szz);
            } else if (eq & (1u << lane)) {
                int pos = tcnt + __popc(eq & below);
                if (pos < KNN) ties[wid][pos] = it*32 + lane;
            }
            m    += __popc(lt);
            tcnt += __popc(eq);
        }
    }
    __syncwarp();
    int need = KNN - m;                              // >= 1, tcnt >= need
    if (lane < need) {
        float4 pt = pts[ties[wid][lane]];
        float dx = pt.x-pi.x, dy = pt.y-pi.y, dz = pt.z-pi.z;
        E[m + lane] = make_float4(dx, dy, dz, 0.f);
        sdx += dx; sdy += dy; sdz += dz;
        sxx = fmaf(dx,dx,sxx); sxy = fmaf(dx,dy,sxy); sxz = fmaf(dx,dz,sxz);
        syy = fmaf(dy,dy,syy); syz = fmaf(dy,dz,syz); szz = fmaf(dz,dz,szz);
    }
    #pragma unroll
    for (int o = 16; o > 0; o >>= 1) {
        sdx += __shfl_xor_sync(~0u, sdx, o); sdy += __shfl_xor_sync(~0u, sdy, o);
        sdz += __shfl_xor_sync(~0u, sdz, o);
        sxx += __shfl_xor_sync(~0u, sxx, o); sxy += __shfl_xor_sync(~0u, sxy, o);
        sxz += __shfl_xor_sync(~0u, sxz, o);
        syy += __shfl_xor_sync(~0u, syy, o); syz += __shfl_xor_sync(~0u, syz, o);
        szz += __shfl_xor_sync(~0u, szz, o);
    }
    if (lane == 0) {
        float px = pi.x, py = pi.y, pz = pi.z;
        float Kf = (float)KNN;
        atomicAdd(&sS1[0], sdx); atomicAdd(&sS1[1], sdy); atomicAdd(&sS1[2], sdz);
        atomicAdd(&sS1[3], Kf*px); atomicAdd(&sS1[4], Kf*py); atomicAdd(&sS1[5], Kf*pz);
        atomicAdd(&sS2[0],  sxx);      atomicAdd(&sS2[1],  sxy);
        atomicAdd(&sS2[2],  sxz);      atomicAdd(&sS2[3],  sdx*px);
        atomicAdd(&sS2[4],  sdx*py);   atomicAdd(&sS2[5],  sdx*pz);
        atomicAdd(&sS2[6],  syy);      atomicAdd(&sS2[7],  syz);
        atomicAdd(&sS2[8],  sdy*px);   atomicAdd(&sS2[9],  sdy*py);
        atomicAdd(&sS2[10], sdy*pz);   atomicAdd(&sS2[11], szz);
        atomicAdd(&sS2[12], sdz*px);   atomicAdd(&sS2[13], sdz*py);
        atomicAdd(&sS2[14], sdz*pz);   atomicAdd(&sS2[15], Kf*px*px);
        atomicAdd(&sS2[16], Kf*px*py); atomicAdd(&sS2[17], Kf*px*pz);
        atomicAdd(&sS2[18], Kf*py*py); atomicAdd(&sS2[19], Kf*py*pz);
        atomicAdd(&sS2[20], Kf*pz*pz);
    }
    __syncthreads();
    if (threadIdx.x < 6)  atomicAdd(&g_S1[threadIdx.x], (double)sS1[threadIdx.x]);
    if (threadIdx.x < 21) atomicAdd(&g_S2[threadIdx.x], (double)sS2[threadIdx.x]);

    __threadfence();
    if (threadIdx.x == 0)
        isLast = (atomicAdd(&g_ctr, 1) == (int)gridDim.x - 1);
    __syncthreads();
    if (isLast) {
        int o = threadIdx.x;
        if (o < CH) {
            const float M = (float)NSAMP;
            float m1[6];
            #pragma unroll
            for (int c = 0; c < 6; c++) m1[c] = (float)g_S1[c] / M;
            float w[6];
            #pragma unroll
            for (int c = 0; c < 6; c++) w[c] = W1[o*6 + c];
            float mean = 0.f;
            #pragma unroll
            for (int c = 0; c < 6; c++) mean = fmaf(w[c], m1[c], mean);
            float e2 = 0.f;
            int q = 0;
            #pragma unroll
            for (int c1 = 0; c1 < 6; c1++)
                #pragma unroll
                for (int c2 = c1; c2 < 6; c2++) {
                    float t2 = w[c1]*w[c2]*((float)g_S2[q] / M);
                    e2 += (c1 == c2) ? t2 : 2.f*t2;
                    q++;
                }
            float var = e2 - mean*mean;
            float aa = g1[o] * rsqrtf(var + (float)BN_EPS);
            g_c1[o] = b1[o] - mean*aa;
            #pragma unroll
            for (int c = 0; c < 6; c++) g_W1f[o*6 + c] = aa*w[c];
        }
        if (threadIdx.x == 0) g_ctr = 0;            // reset for next replay
    }
}

// ---------------- K3: fused MLP, LDS-lean phase B (R12-proven) ---------
#define PPB3 16
__global__ void __launch_bounds__(256, 2) k3_mlp(const float* __restrict__ W2) {
    extern __shared__ float smem[];
    float* sW2  = smem;                              // [c*64+u], 16KB
    float* y1s  = smem + CH*CH;                      // [pw][c*28+k], 57.3KB
    float* ssum = y1s + 8*CH*YPITCH;                 // [64]
    float* ssq  = ssum + CH;                         // [64]

    int t = threadIdx.x;
    if (t < CH) { ssum[t] = 0.f; ssq[t] = 0.f; }
    for (int s = t; s < CH*CH; s += 256) {
        int u = s & 63, c = s >> 6;
        sW2[c*CH + u] = W2[u*CH + c];
    }
    int pa = t >> 6, ca = t & 63;
    float w1r[6];
    #pragma unroll
    for (int c = 0; c < 6; c++) w1r[c] = g_W1f[ca*6 + c];
    float c1v = g_c1[ca];
    int warp = t >> 5, lane = t & 31;
    int ug = lane & 15, kq = lane >> 4;
    int u0 = ug*4, k0 = kq*12;
    float su[4] = {0,0,0,0}, qu[4] = {0,0,0,0};
    __syncthreads();

    for (int ph = 0; ph < 2; ph++) {
        int pbase = blockIdx.x*PPB3 + ph*8;
        #pragma unroll
        for (int pp = 0; pp < 2; pp++) {
            int pw = pa + pp*4;
            int p  = pbase + pw;
            float4 pt = g_packed[p];
            float base = c1v;
            base = fmaf(w1r[3], pt.x, base);
            base = fmaf(w1r[4], pt.y, base);
            base = fmaf(w1r[5], pt.z, base);
            const float4* Ep = &g_E4[(size_t)p*KNN];
            float* yo = &y1s[pw*CH*YPITCH + ca*YPITCH];
            #pragma unroll
            for (int k = 0; k < KNN; k++) {
                float4 v = Ep[k];
                float h = base;
                h = fmaf(w1r[0], v.x, h);
                h = fmaf(w1r[1], v.y, h);
                h = fmaf(w1r[2], v.z, h);
                yo[k] = (h >= 0.f) ? h : SLOPE*h;
            }
            #pragma unroll
            for (int k = KNN; k < 24; k++) yo[k] = 0.f;   // zero pad k20..23
        }
        __syncthreads();
        int p = pbase + warp;
        const float* yb = &y1s[warp*CH*YPITCH];
        unsigned long long acc[4][6];
        #pragma unroll
        for (int uu = 0; uu < 4; uu++)
            #pragma unroll
            for (int kk = 0; kk < 6; kk++) acc[uu][kk] = 0ull;
        #pragma unroll 4
        for (int c = 0; c < CH; c++) {
            float4 wv = *(const float4*)&sW2[c*CH + u0];
            unsigned long long w0 = pack2(wv.x), w1 = pack2(wv.y);
            unsigned long long w2 = pack2(wv.z), w3 = pack2(wv.w);
            const float* yr = yb + c*YPITCH + k0;
            #pragma unroll
            for (int q = 0; q < 3; q++) {
                ulonglong2 yv = *(const ulonglong2*)(yr + 4*q);
                acc[0][2*q]   = fma2(w0, yv.x, acc[0][2*q]);
                acc[1][2*q]   = fma2(w1, yv.x, acc[1][2*q]);
                acc[2][2*q]   = fma2(w2, yv.x, acc[2][2*q]);
                acc[3][2*q]   = fma2(w3, yv.x, acc[3][2*q]);
                acc[0][2*q+1] = fma2(w0, yv.y, acc[0][2*q+1]);
                acc[1][2*q+1] = fma2(w1, yv.y, acc[1][2*q+1]);
                acc[2][2*q+1] = fma2(w2, yv.y, acc[2][2*q+1]);
                acc[3][2*q+1] = fma2(w3, yv.y, acc[3][2*q+1]);
            }
        }
        float mx[4], mn[4];
        #pragma unroll
        for (int uu = 0; uu < 4; uu++) {
            mx[uu] = -CUDART_INF_F; mn[uu] = CUDART_INF_F;
            #pragma unroll
            for (int kk = 0; kk < 6; kk++) {
                bool valid = (kq == 0) || (kk < 4);   // kq=1 kk=4,5 are pads
                float lo, hi;
                unpack2(acc[uu][kk], lo, hi);
                su[uu] += lo + hi;                    // pads add 0: harmless
                qu[uu] = fmaf(lo, lo, fmaf(hi, hi, qu[uu]));
                float cmx = valid ? fmaxf(lo, hi) : -CUDART_INF_F;
                float cmn = valid ? fminf(lo, hi) :  CUDART_INF_F;
                mx[uu] = fmaxf(mx[uu], cmx);
                mn[uu] = fminf(mn[uu], cmn);
            }
        }
        #pragma unroll
        for (int uu = 0; uu < 4; uu++) {
            mx[uu] = fmaxf(mx[uu], __shfl_down_sync(~0u, mx[uu], 16));
            mn[uu] = fminf(mn[uu], __shfl_down_sync(~0u, mn[uu], 16));
        }
        if (lane < 16) {
            *(float4*)&g_hmax[(size_t)p*CH + u0] = make_float4(mx[0],mx[1],mx[2],mx[3]);
            *(float4*)&g_hmin[(size_t)p*CH + u0] = make_float4(mn[0],mn[1],mn[2],mn[3]);
        }
        __syncthreads();                 // y1s reuse next ph
    }
    #pragma unroll
    for (int uu = 0; uu < 4; uu++) {
        atomicAdd(&ssum[u0+uu], su[uu]);
        atomicAdd(&ssq[u0+uu],  qu[uu]);
    }
    __syncthreads();
    if (t < CH) {
        atomicAdd(&g_h2sum[t], (double)ssum[t]);
        atomicAdd(&g_h2sq[t],  (double)ssq[t]);
    }
}

// ---------------- F2: finalize BN2 ----------------
__global__ void f2_fold(const float* __restrict__ g2, const float* __restrict__ b2) {
    int o = threadIdx.x; if (o >= CH) return;
    double M = (double)NSAMP;
    double m = g_h2sum[o] / M;
    double v = g_h2sq[o] / M - m*m;
    double a = (double)g2[o] / sqrt(v + BN_EPS);
    g_a2[o] = (float)a;
    g_c2[o] = (float)((double)b2[o] - m*a);
}

// ---------------- K5: BN2+lrelu via monotone max/min + transpose -------
__global__ void k5_out(float* __restrict__ out) {
    __shared__ float tile[32][33];
    int b = blockIdx.z;
    int n0 = blockIdx.x*32, o0 = blockIdx.y*32;
    int tx = threadIdx.x, ty = threadIdx.y;
    #pragma unroll
    for (int r = 0; r < 4; r++) {
        int n = n0 + ty + 8*r, o = o0 + tx;
        float a = g_a2[o], c = g_c2[o];
        size_t idx = ((size_t)(b*NPTS + n))*CH + o;
        float h = (a >= 0.f) ? g_hmax[idx] : g_hmin[idx];
        float v = fmaf(a, h, c);
        tile[ty + 8*r][tx] = (v >= 0.f) ? v : SLOPE*v;
    }
    __syncthreads();
    #pragma unroll
    for (int r = 0; r < 4; r++) {
        int o = o0 + ty + 8*r, n = n0 + tx;
        out[((size_t)(b*CH + o))*NPTS + n] = tile[tx][ty + 8*r];
    }
}

// ---------------- launch ----------------
extern "C" void kernel_launch(void* const* d_in, const int* in_sizes, int n_in,
                              void* d_out, int out_size) {
    const float* a  = (const float*)d_in[0];
    const float* W1 = (const float*)d_in[1];
    const float* g1 = (const float*)d_in[2];
    const float* b1 = (const float*)d_in[3];
    const float* W2 = (const float*)d_in[4];
    const float* g2 = (const float*)d_in[5];
    const float* b2 = (const float*)d_in[6];
    float* out = (float*)d_out;

    const int K3_SMEM = (CH*CH + 8*CH*YPITCH + 2*CH + 32) * 4;  // ~74.5KB
    cudaFuncSetAttribute(k3_mlp, cudaFuncAttributeMaxDynamicSharedMemorySize, K3_SMEM);

    // 2 dummies: ncu capture lands on launch index 3 == k1_seg
    kdummy<<<1, 32>>>();                             // index 0
    kdummy<<<1, 32>>>();                             // index 1
    k0_pack<<<128, 256>>>(a);                        // index 2
    k1_seg<<<512, 128>>>();                          // index 3  <- profiled
    k1_emit<<<4096, 256>>>(W1, g1, b1);              // index 4
    k3_mlp<<<2048, 256, K3_SMEM>>>(W2);              // index 5
    f2_fold<<<1, 64>>>(g2, b2);                      // index 6
    k5_out<<<dim3(128, 2, NB), dim3(32, 8)>>>(out);  // index 7
}

// round 17
// speedup vs baseline: 1.0826x; 1.0758x over previous
#include <cuda_runtime.h>
#include <math_constants.h>
#include <stdint.h>

#define NB    8
#define NPTS  4096
#define KNN   20
#define CH    64
#define NSAMP (NB*NPTS*KNN)      // 655360
#define NQ    (NB*NPTS)          // 32768 queries
#define NSEG  2
#define SEGN  (NPTS/NSEG)        // 2048
#define BN_EPS 1e-5
#define SLOPE  0.2f
#define YPITCH 28                // + 4-word skew every 8 rows (bank fix)
#define PROW(ca) ((ca)*YPITCH + (((ca) >> 3) << 2))
#define PSTRIDE 1820             // 63*28+28 = 1792 + 24 used <= 1820, mult of 4

// ---------------- device scratch ----------------
__device__ float4 g_packed[NB*NPTS];                 // (x,y,z,|p|^2)
__device__ float4 g_E4[NSAMP];                       // edge diffs (d3, 0)
__device__ float  g_dl[NSEG*NQ*KNN];                 // per-segment sorted dists
__device__ double g_S1[6];
__device__ double g_S2[21];
__device__ float  g_W1f[CH*6];
__device__ float  g_c1[CH];
__device__ double g_h2sum[CH];
__device__ double g_h2sq[CH];
__device__ float  g_a2[CH], g_c2[CH];
__device__ float  g_hmax[(size_t)NQ*CH];
__device__ float  g_hmin[(size_t)NQ*CH];
__device__ int    g_ctr;

// ---------------- packed f32x2 helpers ----------------
__device__ __forceinline__ unsigned long long fma2(unsigned long long a,
                                                   unsigned long long b,
                                                   unsigned long long c) {
    unsigned long long d;
    asm("fma.rn.f32x2 %0, %1, %2, %3;" : "=l"(d) : "l"(a), "l"(b), "l"(c));
    return d;
}
__device__ __forceinline__ unsigned long long pack2(float x) {
    unsigned long long d;
    asm("mov.b64 %0, {%1, %1};" : "=l"(d) : "f"(x));
    return d;
}
__device__ __forceinline__ void unpack2(unsigned long long v, float& lo, float& hi) {
    asm("mov.b64 {%0, %1}, %2;" : "=f"(lo), "=f"(hi) : "l"(v));
}

// ---------------- K0: pack points + zero accumulators ----------------
__global__ void k0_pack(const float* __restrict__ a) {
    int t = blockIdx.x*blockDim.x + threadIdx.x;     // 0..32767
    int b = t / NPTS, n = t % NPTS;
    const float* ab = a + (size_t)b*3*NPTS;
    float x = ab[n], y = ab[NPTS+n], z = ab[2*NPTS+n];
    float sq = fmaf(z,z, fmaf(y,y, x*x));
    g_packed[t] = make_float4(x,y,z,sq);
    if (blockIdx.x == 0) {
        int i = threadIdx.x;
        if (i == 0)  g_ctr = 0;
        if (i < 6)   g_S1[i] = 0.0;
        if (i < 21)  g_S2[i] = 0.0;
        if (i < CH) { g_h2sum[i] = 0.0; g_h2sq[i] = 0.0; }
    }
}

// ---------------- K1a: segmented distance-only top-20 (R12-proven) -----
// d' = sq_j - 2*dot(p_i,p_j). Branchless sorted-insert network:
//   dl[t] = min(dl[t], max(d, dl[t-1]))   (exact, 2 FMNMX/slot, no preds)
__global__ void __launch_bounds__(128) k1_seg() {
    int blk = blockIdx.x;                            // 0..511
    int seg = (blk >= 256) ? 1 : 0;
    int qid = (blk & 255)*128 + threadIdx.x;         // 0..32767
    int b = qid / NPTS; int i = qid % NPTS;
    const float4* pts = &g_packed[b*NPTS];
    float4 pi = pts[i];
    float n2x = -2.f*pi.x, n2y = -2.f*pi.y, n2z = -2.f*pi.z;

    float dl[KNN];
    #pragma unroll
    for (int t = 0; t < KNN; t++) dl[t] = CUDART_INF_F;

    int jbase = seg * SEGN;
    for (int j = 0; j < SEGN; j += 8) {
        float dd[8];
        #pragma unroll
        for (int u = 0; u < 8; u++) {
            float4 pj = __ldg(&pts[jbase + j + u]);
            dd[u] = fmaf(n2z, pj.z, fmaf(n2y, pj.y, fmaf(n2x, pj.x, pj.w)));
        }
        #pragma unroll
        for (int u = 0; u < 8; u++) {
            float d = dd[u];
            if (d < dl[KNN-1]) {
                #pragma unroll
                for (int t = KNN-1; t >= 1; t--)
                    dl[t] = fminf(dl[t], fmaxf(d, dl[t-1]));
                dl[0] = fminf(dl[0], d);
            }
        }
    }
    size_t o = ((size_t)seg*NQ + qid)*KNN;
    #pragma unroll
    for (int t = 0; t < KNN; t++) g_dl[o+t] = dl[t];
}

// ---------------- K1b: warp-coop rescan (2x unroll) + moments + fold ---
__global__ void __launch_bounds__(256) k1_emit(const float* __restrict__ W1,
                                               const float* __restrict__ g1,
                                               const float* __restrict__ b1) {
    __shared__ int   ties[8][KNN];
    __shared__ float sS1[6], sS2[21];
    __shared__ int   isLast;
    int wid  = threadIdx.x >> 5;
    int lane = threadIdx.x & 31;
    int qid  = blockIdx.x*8 + wid;                   // one query per warp
    int b = qid / NPTS; int i = qid % NPTS;
    const float4* pts = &g_packed[b*NPTS];
    float4 pi = pts[i];
    float n2x = -2.f*pi.x, n2y = -2.f*pi.y, n2z = -2.f*pi.z;

    if (threadIdx.x < 6)  sS1[threadIdx.x] = 0.f;
    if (threadIdx.x < 21) sS2[threadIdx.x] = 0.f;
    __syncthreads();

    float thr = 0.f;
    if (lane == 0) {
        const float* A = &g_dl[(size_t)qid*KNN];
        const float* B = &g_dl[((size_t)NQ + qid)*KNN];
        int ia = 0, ib = 0;
        float da = A[0], db = B[0];
        #pragma unroll
        for (int t = 0; t < KNN; t++) {
            bool ta = (da <= db);
            thr = ta ? da : db;
            if (ta) { ia++; da = (ia < KNN) ? A[ia] : CUDART_INF_F; }
            else    { ib++; db = (ib < KNN) ? B[ib] : CUDART_INF_F; }
        }
    }
    thr = __shfl_sync(~0u, thr, 0);

    float4* E = &g_E4[(size_t)qid*KNN];
    int m = 0, tcnt = 0;
    float sdx=0.f, sdy=0.f, sdz=0.f;
    float sxx=0.f, sxy=0.f, sxz=0.f, syy=0.f, syz=0.f, szz=0.f;
    unsigned mybit = 1u << lane;
    unsigned below = mybit - 1u;

    float4 p0 = __ldg(&pts[lane]);
    float4 p1 = __ldg(&pts[32 + lane]);
    for (int it = 0; it < NPTS/64; it++) {
        float4 c0 = p0, c1 = p1;
        if (it < NPTS/64 - 1) {
            p0 = __ldg(&pts[(it+1)*64 + lane]);
            p1 = __ldg(&pts[(it+1)*64 + 32 + lane]);
        }
        float d0 = fmaf(n2z, c0.z, fmaf(n2y, c0.y, fmaf(n2x, c0.x, c0.w)));
        float d1 = fmaf(n2z, c1.z, fmaf(n2y, c1.y, fmaf(n2x, c1.x, c1.w)));
        bool h0 = (d0 <= thr), h1 = (d1 <= thr);
        unsigned any = __ballot_sync(~0u, h0 || h1);
        if (any) {
            // candidate block 0: j in [it*64, it*64+32)
            unsigned lt0 = __ballot_sync(~0u, d0 < thr);
            unsigned le0 = __ballot_sync(~0u, h0);
            unsigned eq0 = le0 & ~lt0;
            if (d0 < thr) {
                float dx = c0.x-pi.x, dy = c0.y-pi.y, dz = c0.z-pi.z;
                E[m + __popc(lt0 & below)] = make_float4(dx, dy, dz, 0.f);
                sdx += dx; sdy += dy; sdz += dz;
                sxx = fmaf(dx,dx,sxx); sxy = fmaf(dx,dy,sxy); sxz = fmaf(dx,dz,sxz);
                syy = fmaf(dy,dy,syy); syz = fmaf(dy,dz,syz); szz = fmaf(dz,dz,szz);
            } else if (eq0 & mybit) {
                int pos = tcnt + __popc(eq0 & below);
                if (pos < KNN) ties[wid][pos] = it*64 + lane;
            }
            m    += __popc(lt0);
            tcnt += __popc(eq0);
            // candidate block 1: j in [it*64+32, it*64+64)
            unsigned lt1 = __ballot_sync(~0u, d1 < thr);
            unsigned le1 = __ballot_sync(~0u, h1);
            unsigned eq1 = le1 & ~lt1;
            if (d1 < thr) {
                float dx = c1.x-pi.x, dy = c1.y-pi.y, dz = c1.z-pi.z;
                E[m + __popc(lt1 & below)] = make_float4(dx, dy, dz, 0.f);
                sdx += dx; sdy += dy; sdz += dz;
                sxx = fmaf(dx,dx,sxx); sxy = fmaf(dx,dy,sxy); sxz = fmaf(dx,dz,sxz);
                syy = fmaf(dy,dy,syy); syz = fmaf(dy,dz,syz); szz = fmaf(dz,dz,szz);
            } else if (eq1 & mybit) {
                int pos = tcnt + __popc(eq1 & below);
                if (pos < KNN) ties[wid][pos] = it*64 + 32 + lane;
            }
            m    += __popc(lt1);
            tcnt += __popc(eq1);
        }
    }
    __syncwarp();
    int need = KNN - m;                              // >= 1, tcnt >= need
    if (lane < need) {
        float4 pt = pts[ties[wid][lane]];
        float dx = pt.x-pi.x, dy = pt.y-pi.y, dz = pt.z-pi.z;
        E[m + lane] = make_float4(dx, dy, dz, 0.f);
        sdx += dx; sdy += dy; sdz += dz;
        sxx = fmaf(dx,dx,sxx); sxy = fmaf(dx,dy,sxy); sxz = fmaf(dx,dz,sxz);
        syy = fmaf(dy,dy,syy); syz = fmaf(dy,dz,syz); szz = fmaf(dz,dz,szz);
    }
    #pragma unroll
    for (int o = 16; o > 0; o >>= 1) {
        sdx += __shfl_xor_sync(~0u, sdx, o); sdy += __shfl_xor_sync(~0u, sdy, o);
        sdz += __shfl_xor_sync(~0u, sdz, o);
        sxx += __shfl_xor_sync(~0u, sxx, o); sxy += __shfl_xor_sync(~0u, sxy, o);
        sxz += __shfl_xor_sync(~0u, sxz, o);
        syy += __shfl_xor_sync(~0u, syy, o); syz += __shfl_xor_sync(~0u, syz, o);
        szz += __shfl_xor_sync(~0u, szz, o);
    }
    if (lane == 0) {
        float px = pi.x, py = pi.y, pz = pi.z;
        float Kf = (float)KNN;
        atomicAdd(&sS1[0], sdx); atomicAdd(&sS1[1], sdy); atomicAdd(&sS1[2], sdz);
        atomicAdd(&sS1[3], Kf*px); atomicAdd(&sS1[4], Kf*py); atomicAdd(&sS1[5], Kf*pz);
        atomicAdd(&sS2[0],  sxx);      atomicAdd(&sS2[1],  sxy);
        atomicAdd(&sS2[2],  sxz);      atomicAdd(&sS2[3],  sdx*px);
        atomicAdd(&sS2[4],  sdx*py);   atomicAdd(&sS2[5],  sdx*pz);
        atomicAdd(&sS2[6],  syy);      atomicAdd(&sS2[7],  syz);
        atomicAdd(&sS2[8],  sdy*px);   atomicAdd(&sS2[9],  sdy*py);
        atomicAdd(&sS2[10], sdy*pz);   atomicAdd(&sS2[11], szz);
        atomicAdd(&sS2[12], sdz*px);   atomicAdd(&sS2[13], sdz*py);
        atomicAdd(&sS2[14], sdz*pz);   atomicAdd(&sS2[15], Kf*px*px);
        atomicAdd(&sS2[16], Kf*px*py); atomicAdd(&sS2[17], Kf*px*pz);
        atomicAdd(&sS2[18], Kf*py*py); atomicAdd(&sS2[19], Kf*py*pz);
        atomicAdd(&sS2[20], Kf*pz*pz);
    }
    __syncthreads();
    if (threadIdx.x < 6)  atomicAdd(&g_S1[threadIdx.x], (double)sS1[threadIdx.x]);
    if (threadIdx.x < 21) atomicAdd(&g_S2[threadIdx.x], (double)sS2[threadIdx.x]);

    __threadfence();
    if (threadIdx.x == 0)
        isLast = (atomicAdd(&g_ctr, 1) == (int)gridDim.x - 1);
    __syncthreads();
    if (isLast) {
        int o = threadIdx.x;
        if (o < CH) {
            const float M = (float)NSAMP;
            float m1[6];
            #pragma unroll
            for (int c = 0; c < 6; c++) m1[c] = (float)g_S1[c] / M;
            float w[6];
            #pragma unroll
            for (int c = 0; c < 6; c++) w[c] = W1[o*6 + c];
            float mean = 0.f;
            #pragma unroll
            for (int c = 0; c < 6; c++) mean = fmaf(w[c], m1[c], mean);
            float e2 = 0.f;
            int q = 0;
            #pragma unroll
            for (int c1 = 0; c1 < 6; c1++)
                #pragma unroll
                for (int c2 = c1; c2 < 6; c2++) {
                    float t2 = w[c1]*w[c2]*((float)g_S2[q] / M);
                    e2 += (c1 == c2) ? t2 : 2.f*t2;
                    q++;
                }
            float var = e2 - mean*mean;
            float aa = g1[o] * rsqrtf(var + (float)BN_EPS);
            g_c1[o] = b1[o] - mean*aa;
            #pragma unroll
            for (int c = 0; c < 6; c++) g_W1f[o*6 + c] = aa*w[c];
        }
        if (threadIdx.x == 0) g_ctr = 0;            // reset for next replay
    }
}

// ---------------- K3: fused MLP, bank-skewed y1 staging ---------------
// Row start = ca*28 + (ca>>3)*4: lanes ca, ca+8, ca+16, ca+24 hit banks
// {0,4,8,12}+k mod 32 -> phase-A scalar STS are conflict-free. Phase-B
// reads stay 16B-aligned broadcasts.
#define PPB3 16
__global__ void __launch_bounds__(256, 2) k3_mlp(const float* __restrict__ W2) {
    extern __shared__ float smem[];
    float* sW2  = smem;                              // [c*64+u], 16KB
    float* y1s  = smem + CH*CH;                      // [pw][PROW(c)+k], 56.9KB
    float* ssum = y1s + 8*PSTRIDE;                   // [64]
    float* ssq  = ssum + CH;                         // [64]

    int t = threadIdx.x;
    if (t < CH) { ssum[t] = 0.f; ssq[t] = 0.f; }
    for (int s = t; s < CH*CH; s += 256) {
        int u = s & 63, c = s >> 6;
        sW2[c*CH + u] = W2[u*CH + c];
    }
    int pa = t >> 6, ca = t & 63;
    float w1r[6];
    #pragma unroll
    for (int c = 0; c < 6; c++) w1r[c] = g_W1f[ca*6 + c];
    float c1v = g_c1[ca];
    int warp = t >> 5, lane = t & 31;
    int ug = lane & 15, kq = lane >> 4;
    int u0 = ug*4, k0 = kq*12;
    float su[4] = {0,0,0,0}, qu[4] = {0,0,0,0};
    __syncthreads();

    for (int ph = 0; ph < 2; ph++) {
        int pbase = blockIdx.x*PPB3 + ph*8;
        #pragma unroll
        for (int pp = 0; pp < 2; pp++) {
            int pw = pa + pp*4;
            int p  = pbase + pw;
            float4 pt = g_packed[p];
            float base = c1v;
            base = fmaf(w1r[3], pt.x, base);
            base = fmaf(w1r[4], pt.y, base);
            base = fmaf(w1r[5], pt.z, base);
            const float4* Ep = &g_E4[(size_t)p*KNN];
            float* yo = &y1s[pw*PSTRIDE + PROW(ca)];
            #pragma unroll
            for (int k = 0; k < KNN; k++) {
                float4 v = Ep[k];
                float h = base;
                h = fmaf(w1r[0], v.x, h);
                h = fmaf(w1r[1], v.y, h);
                h = fmaf(w1r[2], v.z, h);
                yo[k] = (h >= 0.f) ? h : SLOPE*h;
            }
            #pragma unroll
            for (int k = KNN; k < 24; k++) yo[k] = 0.f;   // zero pad k20..23
        }
        __syncthreads();
        int p = pbase + warp;
        const float* yb = &y1s[warp*PSTRIDE];
        unsigned long long acc[4][6];
        #pragma unroll
        for (int uu = 0; uu < 4; uu++)
            #pragma unroll
            for (int kk = 0; kk < 6; kk++) acc[uu][kk] = 0ull;
        #pragma unroll 4
        for (int c = 0; c < CH; c++) {
            float4 wv = *(const float4*)&sW2[c*CH + u0];
            unsigned long long w0 = pack2(wv.x), w1 = pack2(wv.y);
            unsigned long long w2 = pack2(wv.z), w3 = pack2(wv.w);
            const float* yr = yb + PROW(c) + k0;
            #pragma unroll
            for (int q = 0; q < 3; q++) {
                ulonglong2 yv = *(const ulonglong2*)(yr + 4*q);
                acc[0][2*q]   = fma2(w0, yv.x, acc[0][2*q]);
                acc[1][2*q]   = fma2(w1, yv.x, acc[1][2*q]);
                acc[2][2*q]   = fma2(w2, yv.x, acc[2][2*q]);
                acc[3][2*q]   = fma2(w3, yv.x, acc[3][2*q]);
                acc[0][2*q+1] = fma2(w0, yv.y, acc[0][2*q+1]);
                acc[1][2*q+1] = fma2(w1, yv.y, acc[1][2*q+1]);
                acc[2][2*q+1] = fma2(w2, yv.y, acc[2][2*q+1]);
                acc[3][2*q+1] = fma2(w3, yv.y, acc[3][2*q+1]);
            }
        }
        float mx[4], mn[4];
        #pragma unroll
        for (int uu = 0; uu < 4; uu++) {
            mx[uu] = -CUDART_INF_F; mn[uu] = CUDART_INF_F;
            #pragma unroll
            for (int kk = 0; kk < 6; kk++) {
                bool valid = (kq == 0) || (kk < 4);   // kq=1 kk=4,5 are pads
                float lo, hi;
                unpack2(acc[uu][kk], lo, hi);
                su[uu] += lo + hi;                    // pads add 0: harmless
                qu[uu] = fmaf(lo, lo, fmaf(hi, hi, qu[uu]));
                float cmx = valid ? fmaxf(lo, hi) : -CUDART_INF_F;
                float cmn = valid ? fminf(lo, hi) :  CUDART_INF_F;
                mx[uu] = fmaxf(mx[uu], cmx);
                mn[uu] = fminf(mn[uu], cmn);
            }
        }
        #pragma unroll
        for (int uu = 0; uu < 4; uu++) {
            mx[uu] = fmaxf(mx[uu], __shfl_down_sync(~0u, mx[uu], 16));
            mn[uu] = fminf(mn[uu], __shfl_down_sync(~0u, mn[uu], 16));
        }
        if (lane < 16) {
            *(float4*)&g_hmax[(size_t)p*CH + u0] = make_float4(mx[0],mx[1],mx[2],mx[3]);
            *(float4*)&g_hmin[(size_t)p*CH + u0] = make_float4(mn[0],mn[1],mn[2],mn[3]);
        }
        __syncthreads();                 // y1s reuse next ph
    }
    #pragma unroll
    for (int uu = 0; uu < 4; uu++) {
        atomicAdd(&ssum[u0+uu], su[uu]);
        atomicAdd(&ssq[u0+uu],  qu[uu]);
    }
    __syncthreads();
    if (t < CH) {
        atomicAdd(&g_h2sum[t], (double)ssum[t]);
        atomicAdd(&g_h2sq[t],  (double)ssq[t]);
    }
}

// ---------------- F2: finalize BN2 ----------------
__global__ void f2_fold(const float* __restrict__ g2, const float* __restrict__ b2) {
    int o = threadIdx.x; if (o >= CH) return;
    double M = (double)NSAMP;
    double m = g_h2sum[o] / M;
    double v = g_h2sq[o] / M - m*m;
    double a = (double)g2[o] / sqrt(v + BN_EPS);
    g_a2[o] = (float)a;
    g_c2[o] = (float)((double)b2[o] - m*a);
}

// ---------------- K5: BN2+lrelu via monotone max/min + transpose -------
__global__ void k5_out(float* __restrict__ out) {
    __shared__ float tile[32][33];
    int b = blockIdx.z;
    int n0 = blockIdx.x*32, o0 = blockIdx.y*32;
    int tx = threadIdx.x, ty = threadIdx.y;
    #pragma unroll
    for (int r = 0; r < 4; r++) {
        int n = n0 + ty + 8*r, o = o0 + tx;
        float a = g_a2[o], c = g_c2[o];
        size_t idx = ((size_t)(b*NPTS + n))*CH + o;
        float h = (a >= 0.f) ? g_hmax[idx] : g_hmin[idx];
        float v = fmaf(a, h, c);
        tile[ty + 8*r][tx] = (v >= 0.f) ? v : SLOPE*v;
    }
    __syncthreads();
    #pragma unroll
    for (int r = 0; r < 4; r++) {
        int o = o0 + ty + 8*r, n = n0 + tx;
        out[((size_t)(b*CH + o))*NPTS + n] = tile[tx][ty + 8*r];
    }
}

// ---------------- launch ----------------
extern "C" void kernel_launch(void* const* d_in, const int* in_sizes, int n_in,
                              void* d_out, int out_size) {
    const float* a  = (const float*)d_in[0];
    const float* W1 = (const float*)d_in[1];
    const float* g1 = (const float*)d_in[2];
    const float* b1 = (const float*)d_in[3];
    const float* W2 = (const float*)d_in[4];
    const float* g2 = (const float*)d_in[5];
    const float* b2 = (const float*)d_in[6];
    float* out = (float*)d_out;

    const int K3_SMEM = (CH*CH + 8*PSTRIDE + 2*CH + 32) * 4;  // ~73.6KB
    cudaFuncSetAttribute(k3_mlp, cudaFuncAttributeMaxDynamicSharedMemorySize, K3_SMEM);

    k0_pack<<<128, 256>>>(a);                        // index 0
    k1_seg<<<512, 128>>>();                          // index 1
    k1_emit<<<4096, 256>>>(W1, g1, b1);              // index 2
    k3_mlp<<<2048, 256, K3_SMEM>>>(W2);              // index 3  <- profiled
    f2_fold<<<1, 64>>>(g2, b2);                      // index 4
    k5_out<<<dim3(128, 2, NB), dim3(32, 8)>>>(out);  // index 5
}